// round 2
// baseline (speedup 1.0000x reference)
#include <cuda_runtime.h>
#include <cstdint>
#include <math.h>

typedef unsigned long long ull;

#define NN 512
#define DD 64
#define BB 8
#define KSEL 256
#define XP 258   // padded pitch for transposed x tile (floats)

// Scratch (static __device__ arrays: no allocation allowed)
__device__ float g_L[(size_t)BB * NN * NN];   // logits  8 MB
__device__ float g_h[(size_t)BB * NN * DD];   // h after selu
__device__ float g_s[(size_t)BB * NN];        // sigmoid scores

// Fast accurate-enough tanh: ex2.approx + rcp.approx with one Newton step.
// tanh(|x|) = (1-t)/(1+t), t = 2^(-2|x|*log2e).  abs err ~1e-7.
__device__ __forceinline__ float fast_tanh(float x) {
    float ax = fabsf(x);
    float t;
    asm("ex2.approx.f32 %0, %1;" : "=f"(t) : "f"(ax * -2.8853900817779268f));
    float u = 1.0f + t;
    float r;
    asm("rcp.approx.f32 %0, %1;" : "=f"(r) : "f"(u));
    r = r * fmaf(-u, r, 2.0f);          // Newton refine
    float v = (1.0f - t) * r;           // in [0,1)
    return copysignf(v, x);
}

// ---------------------------------------------------------------------------
// Kernel 1: logits[b][i][j] = sum_o v[o]*tanh( sum_d x[b,i,d]*W[d,o]*x[b,j,d] + b[o] )
// Symmetric: CTA (b,i) computes k=(j-i) mod 512 in [0,255] (+256 if i<256),
// writes both [i][j] and [j][i]. Inner GEMM uses packed fma.rn.f32x2.
// ---------------------------------------------------------------------------
__global__ __launch_bounds__(256, 2) void k1_logits(
    const float* __restrict__ x, const float* __restrict__ attw,
    const float* __restrict__ attb, const float* __restrict__ attv)
{
    extern __shared__ float smem[];
    float* xT  = smem;                         // [64][XP], jloc 0..256 used
    ull*   Wp2 = (ull*)(smem + 64 * XP);       // [64][64] lane-duplicated W'
    float* red = (float*)(Wp2 + 64 * 64);      // [8][256]
    float* vv  = red + 8 * 256;                // [64]
    float* bbv = vv + 64;                      // [64]

    const int i = blockIdx.x, b = blockIdx.y;
    const int tid = threadIdx.x;
    const int jg = tid & 31, og = tid >> 5;

    // Load x window (rows i..i+256 mod 512) transposed into smem (coalesced)
    for (int idx = tid; idx < 257 * 64; idx += 256) {
        int r = idx >> 6, d = idx & 63;
        int g = (i + r) & (NN - 1);
        xT[d * XP + r] = x[((size_t)b * NN + g) * DD + d];
    }
    if (tid < 64) { vv[tid] = attv[tid]; bbv[tid] = attb[tid]; }
    __syncthreads();

    // W'[d][o] = x[b,i,d] * W[d,o], duplicated into both f32x2 lanes
    for (int idx = tid; idx < 64 * 64; idx += 256) {
        int d = idx >> 6;
        float w = xT[d * XP] * attw[idx];
        ull wd; asm("mov.b64 %0,{%1,%1};" : "=l"(wd) : "f"(w));
        Wp2[idx] = wd;
    }
    __syncthreads();

    // Register tile: 8 j (4 pairs) x 8 o per thread; 256 threads cover 256 j x 64 o
    ull acc[4][8];
    #pragma unroll
    for (int r = 0; r < 4; r++)
        #pragma unroll
        for (int c = 0; c < 8; c++) acc[r][c] = 0ull;

    #pragma unroll 8
    for (int d = 0; d < 64; d++) {
        ull xp[4];
        #pragma unroll
        for (int r = 0; r < 4; r++)
            xp[r] = *(const ull*)&xT[d * XP + 2 * jg + 64 * r];
        // W' for this warp's 8 o values: 4x LDS.128 (broadcast within warp)
        ulonglong2 w0 = *(const ulonglong2*)&Wp2[d * 64 + og * 8 + 0];
        ulonglong2 w1 = *(const ulonglong2*)&Wp2[d * 64 + og * 8 + 2];
        ulonglong2 w2 = *(const ulonglong2*)&Wp2[d * 64 + og * 8 + 4];
        ulonglong2 w3 = *(const ulonglong2*)&Wp2[d * 64 + og * 8 + 6];
        ull wv[8] = {w0.x, w0.y, w1.x, w1.y, w2.x, w2.y, w3.x, w3.y};
        #pragma unroll
        for (int r = 0; r < 4; r++)
            #pragma unroll
            for (int c = 0; c < 8; c++)
                asm("fma.rn.f32x2 %0, %1, %2, %0;"
                    : "+l"(acc[r][c]) : "l"(xp[r]), "l"(wv[c]));
    }

    // Epilogue: tanh + reduce over o (v-weighted), partial per og group
    #pragma unroll
    for (int r = 0; r < 4; r++) {
        float plo = 0.f, phi = 0.f;
        #pragma unroll
        for (int c = 0; c < 8; c++) {
            int o = og * 8 + c;
            float lo, hi;
            asm("mov.b64 {%0,%1}, %2;" : "=f"(lo), "=f"(hi) : "l"(acc[r][c]));
            plo += vv[o] * fast_tanh(lo + bbv[o]);
            phi += vv[o] * fast_tanh(hi + bbv[o]);
        }
        int jloc = 2 * jg + 64 * r;
        red[og * 256 + jloc]     = plo;
        red[og * 256 + jloc + 1] = phi;
    }
    __syncthreads();
    {
        float s = 0.f;
        #pragma unroll
        for (int g = 0; g < 8; g++) s += red[g * 256 + tid];
        int jglob = (i + tid) & (NN - 1);
        g_L[((size_t)b * NN + i) * NN + jglob] = s;
        g_L[((size_t)b * NN + jglob) * NN + i] = s;   // symmetric mirror
    }

    // Tail k=256: single writer (i<256) for determinism
    if (i < 256) {
        __syncthreads();
        if (tid < 64) {
            float q = bbv[tid];
            #pragma unroll 8
            for (int d = 0; d < 64; d++)
                q += (xT[d * XP] * attw[d * 64 + tid]) * xT[d * XP + 256];
            red[tid] = vv[tid] * fast_tanh(q);
        }
        __syncthreads();
        if (tid == 0) {
            float s = 0.f;
            for (int o = 0; o < 64; o++) s += red[o];
            int jglob = (i + 256) & (NN - 1);
            g_L[((size_t)b * NN + i) * NN + jglob] = s;
            g_L[((size_t)b * NN + jglob) * NN + i] = s;
        }
    }
}

// ---------------------------------------------------------------------------
// Kernel 2 (tiled): CTA = (itile of 32 rows, b). Smem holds the 32x512 logit
// tile and the full x_b (512x64). Row softmax, agg GEMM, h/BN/selu, scores.
// ---------------------------------------------------------------------------
#define ITILE 32
__global__ __launch_bounds__(256, 1) void k2_head(
    const float* __restrict__ x,
    const float* __restrict__ pwa_w, const float* __restrict__ pwa_b,
    const float* __restrict__ pwo_w, const float* __restrict__ pwo_b,
    const float* __restrict__ gamma, const float* __restrict__ beta,
    const float* __restrict__ poolw, const float* __restrict__ poolb)
{
    extern __shared__ float s2[];
    float* att = s2;                       // [32][512]
    float* xs  = s2 + ITILE * NN;          // [512][64]
    float* inv = xs + NN * DD;             // [32]
    float* agg = inv + ITILE;              // [32][64]
    float* hsm = agg + ITILE * DD;         // [32][64]

    const int itile = blockIdx.x, b = blockIdx.y;
    const int tid = threadIdx.x;
    const int wid = tid >> 5, lane = tid & 31;

    // Load logit tile + full x_b into smem (float4, coalesced)
    {
        const float4* Ls = (const float4*)(g_L + ((size_t)b * NN + itile * ITILE) * NN);
        float4* Ld = (float4*)att;
        for (int idx = tid; idx < ITILE * NN / 4; idx += 256) Ld[idx] = Ls[idx];
        const float4* Xs = (const float4*)(x + (size_t)b * NN * DD);
        float4* Xd = (float4*)xs;
        for (int idx = tid; idx < NN * DD / 4; idx += 256) Xd[idx] = Xs[idx];
    }
    __syncthreads();

    // Row softmax: max, then exp in place (unnormalized), 1/sum per row
    for (int r = wid; r < ITILE; r += 8) {
        float* row = att + r * NN;
        float m = -1e30f;
        #pragma unroll 4
        for (int j = lane; j < NN; j += 32) m = fmaxf(m, row[j]);
        #pragma unroll
        for (int off = 16; off; off >>= 1) m = fmaxf(m, __shfl_xor_sync(~0u, m, off));
        float ssum = 0.f;
        #pragma unroll 4
        for (int j = lane; j < NN; j += 32) {
            float e = __expf(row[j] - m);
            row[j] = e;
            ssum += e;
        }
        #pragma unroll
        for (int off = 16; off; off >>= 1) ssum += __shfl_xor_sync(~0u, ssum, off);
        if (lane == 0) inv[r] = 1.0f / ssum;
    }
    __syncthreads();

    // agg[i][d] = inv[i] * sum_j att[i][j] * xs[j][d]
    const int d = tid & 63, ig = tid >> 6;   // ig in 0..3, 8 rows each
    {
        float acc[8] = {0, 0, 0, 0, 0, 0, 0, 0};
        for (int j = 0; j < NN; j += 4) {
            float x0 = xs[(j + 0) * DD + d];
            float x1 = xs[(j + 1) * DD + d];
            float x2 = xs[(j + 2) * DD + d];
            float x3 = xs[(j + 3) * DD + d];
            #pragma unroll
            for (int s = 0; s < 8; s++) {
                float4 a = *(const float4*)&att[(ig * 8 + s) * NN + j];
                acc[s] = fmaf(a.x, x0, acc[s]);
                acc[s] = fmaf(a.y, x1, acc[s]);
                acc[s] = fmaf(a.z, x2, acc[s]);
                acc[s] = fmaf(a.w, x3, acc[s]);
            }
        }
        #pragma unroll
        for (int s = 0; s < 8; s++)
            agg[(ig * 8 + s) * DD + d] = acc[s] * inv[ig * 8 + s];
    }
    __syncthreads();

    // h = agg@pwa + x_i@pwo + biases, BN(eval) scale, selu
    {
        const int o = d;  // same mapping: o = tid&63
        float hv[8];
        float pb = pwa_b[o] + pwo_b[o];
        #pragma unroll
        for (int s = 0; s < 8; s++) hv[s] = pb;
        #pragma unroll 4
        for (int dd = 0; dd < 64; dd++) {
            float wa = pwa_w[dd * 64 + o];
            float wo = pwo_w[dd * 64 + o];
            #pragma unroll
            for (int s = 0; s < 8; s++) {
                int i = ig * 8 + s;
                hv[s] = fmaf(agg[i * DD + dd], wa, hv[s]);
                hv[s] = fmaf(xs[(itile * ITILE + i) * DD + dd], wo, hv[s]);
            }
        }
        const float BNS = 0.99999500003749969f;  // 1/sqrt(1+1e-5)
        float gam = gamma[o] * BNS, bet = beta[o];
        const float SC = 1.0507009873554804934193349852946f;
        const float AL = 1.6732632423543772848170429916717f;
        #pragma unroll
        for (int s = 0; s < 8; s++) {
            float h = fmaf(hv[s], gam, bet);
            h = h > 0.f ? SC * h : SC * AL * expm1f(h);
            hsm[(ig * 8 + s) * DD + o] = h;
        }
    }
    __syncthreads();

    // Pool scores (accurate exp for rank stability) + write h
    if (tid < ITILE) {
        float z = poolb[0];
        #pragma unroll 8
        for (int oo = 0; oo < 64; oo++) z = fmaf(hsm[tid * 64 + oo], poolw[oo], z);
        g_s[(size_t)b * NN + itile * ITILE + tid] = 1.0f / (1.0f + expf(-z));
    }
    {
        float* gh = g_h + ((size_t)b * NN + itile * ITILE) * DD;
        for (int idx = tid; idx < ITILE * DD; idx += 256) gh[idx] = hsm[idx];
    }
}

// ---------------------------------------------------------------------------
// Kernel 3: per batch, descending top-256 (stable: lower idx wins ties),
// gather out[b][r] = h[b][idx_r] * score[idx_r]
// ---------------------------------------------------------------------------
__global__ __launch_bounds__(512) void k3_topk(float* __restrict__ out)
{
    __shared__ ull keys[NN];
    const int b = blockIdx.x, tid = threadIdx.x;
    {
        float sc = g_s[(size_t)b * NN + tid];
        keys[tid] = ((ull)__float_as_uint(sc) << 32) | (ull)(unsigned)(511 - tid);
    }
    __syncthreads();
    for (int k = 2; k <= NN; k <<= 1) {
        for (int j = k >> 1; j > 0; j >>= 1) {
            int ixj = tid ^ j;
            if (ixj > tid) {
                ull a = keys[tid], c = keys[ixj];
                bool asc = (tid & k) == 0;
                if ((a > c) == asc) { keys[tid] = c; keys[ixj] = a; }
            }
            __syncthreads();
        }
    }
    const int r = tid >> 1, ho = (tid & 1) * 32;
    ull key = keys[(NN - 1) - r];
    float sc = __uint_as_float((unsigned)(key >> 32));
    int idx = 511 - (int)(key & 0xffffffffu);
    const float* hr = &g_h[((size_t)b * NN + idx) * DD];
    float* orow = &out[((size_t)b * KSEL + r) * DD];
    #pragma unroll
    for (int c = 0; c < 32; c++)
        orow[ho + c] = hr[ho + c] * sc;
}

// ---------------------------------------------------------------------------
extern "C" void kernel_launch(void* const* d_in, const int* in_sizes, int n_in,
                              void* d_out, int out_size)
{
    (void)in_sizes; (void)n_in; (void)out_size;
    const float* x      = (const float*)d_in[0];
    const float* attw   = (const float*)d_in[1];
    const float* attb   = (const float*)d_in[2];
    const float* attv   = (const float*)d_in[3];
    const float* pwa_w  = (const float*)d_in[4];
    const float* pwa_b  = (const float*)d_in[5];
    const float* pwo_w  = (const float*)d_in[6];
    const float* pwo_b  = (const float*)d_in[7];
    const float* gamma  = (const float*)d_in[8];
    const float* beta   = (const float*)d_in[9];
    const float* poolw  = (const float*)d_in[10];
    const float* poolb  = (const float*)d_in[11];

    const int SMEM1 = (64 * XP + 2 * 64 * 64 + 8 * 256 + 128) * (int)sizeof(float);
    cudaFuncSetAttribute(k1_logits, cudaFuncAttributeMaxDynamicSharedMemorySize, SMEM1);
    const int SMEM2 = (ITILE * NN + NN * DD + ITILE + 2 * ITILE * DD) * (int)sizeof(float);
    cudaFuncSetAttribute(k2_head, cudaFuncAttributeMaxDynamicSharedMemorySize, SMEM2);

    dim3 g1(NN, BB);
    k1_logits<<<g1, 256, SMEM1>>>(x, attw, attb, attv);
    dim3 g2(NN / ITILE, BB);
    k2_head<<<g2, 256, SMEM2>>>(x, pwa_w, pwa_b, pwo_w, pwo_b, gamma, beta, poolw, poolb);
    k3_topk<<<BB, NN>>>((float*)d_out);
}